// round 5
// baseline (speedup 1.0000x reference)
#include <cuda_runtime.h>

// ShadingLayer: out[b,c,h,w] = sum_k L[b,c,k] * H_k(n[b,:,h,w])
// R4 = R2 (2 float4-groups/thread, MLP=6, streaming hints) +
//      block-shared coefficient fold + __launch_bounds__(256,7) occupancy cap.
//
// d_in[0]: recnormalch fp32 (64,3,512,512)
// d_in[1]: fc_light    fp32 (64,27)
// d_out  : fp32 (64,3,512,512)

#define C1f 0.8862269254527580f
#define C2f 1.0233267079464885f
#define C3f 0.2477079561003757f
#define C4f 0.8580855308097834f
#define C5f 0.4290427654048917f

static __device__ __forceinline__ float4 ldcs4(const float* p) {
    return __ldcs(reinterpret_cast<const float4*>(p));
}
static __device__ __forceinline__ void stcs4(float* p, float4 v) {
    __stcs(reinterpret_cast<float4*>(p), v);
}

__global__ __launch_bounds__(256, 7)
void shading_kernel(const float* __restrict__ nrm,
                    const float* __restrict__ light,
                    float* __restrict__ out) {
    constexpr int HW = 512 * 512;          // pixels per plane
    // 65536 float4-groups/plane; 512 groups per block -> 128 blocks/batch
    const unsigned bid = blockIdx.x;
    const int b   = bid >> 7;              // batch
    const int blk = bid & 127;             // block within batch
    const int v0  = blk * 512 + threadIdx.x;

    // ---- issue all 6 data loads FIRST (independent of smem) ----
    const float* p0 = nrm + (size_t)b * 3 * HW + (size_t)v0 * 4;
    const float* p1 = p0 + 1024;           // +256 groups
    float4 X0 = ldcs4(p0);
    float4 Y0 = ldcs4(p0 + HW);
    float4 Z0 = ldcs4(p0 + 2 * HW);
    float4 X1 = ldcs4(p1);
    float4 Y1 = ldcs4(p1 + HW);
    float4 Z1 = ldcs4(p1 + 2 * HW);

    // ---- block-cooperative coefficient load + fold ----
    __shared__ float sa[27];               // folded a[c*9+k]
    if (threadIdx.x < 27) {
        const int k = threadIdx.x % 9;
        const float ck = (k == 0) ? C1f
                       : (k <= 3) ? C2f
                       : (k == 4) ? C3f
                       : (k == 7) ? C5f
                       : C4f;              // k = 5,6,8
        sa[threadIdx.x] = ck * __ldg(light + b * 27 + threadIdx.x);
    }
    __syncthreads();

    float a[3][9];
    #pragma unroll
    for (int i = 0; i < 27; i++) a[i / 9][i % 9] = sa[i];

    float* q = out + (size_t)b * 3 * HW + (size_t)v0 * 4;

    #pragma unroll
    for (int g = 0; g < 2; g++) {
        const float4 X = g ? X1 : X0;
        const float4 Y = g ? Y1 : Y0;
        const float4 Z = g ? Z1 : Z0;
        const float xs[4] = {X.x, X.y, X.z, X.w};
        const float ys[4] = {Y.x, Y.y, Y.z, Y.w};
        const float zs[4] = {Z.x, Z.y, Z.z, Z.w};
        float o[3][4];

        #pragma unroll
        for (int j = 0; j < 4; j++) {
            const float x = xs[j], y = ys[j], z = zs[j];
            const float xx = x * x;
            const float yy = y * y;
            const float b5 = 2.0f * z * z - xx - yy;
            const float b6 = x * z;
            const float b7 = y * z;
            const float b8 = xx - yy;
            const float b9 = x * y;
            #pragma unroll
            for (int c = 0; c < 3; c++) {
                float r = a[c][0];
                r = fmaf(a[c][1], z,  r);
                r = fmaf(a[c][2], x,  r);
                r = fmaf(a[c][3], y,  r);
                r = fmaf(a[c][4], b5, r);
                r = fmaf(a[c][5], b6, r);
                r = fmaf(a[c][6], b7, r);
                r = fmaf(a[c][7], b8, r);
                r = fmaf(a[c][8], b9, r);
                o[c][j] = r;
            }
        }

        float* qq = g ? (q + 1024) : q;
        stcs4(qq,          make_float4(o[0][0], o[0][1], o[0][2], o[0][3]));
        stcs4(qq + HW,     make_float4(o[1][0], o[1][1], o[1][2], o[1][3]));
        stcs4(qq + 2 * HW, make_float4(o[2][0], o[2][1], o[2][2], o[2][3]));
    }
}

extern "C" void kernel_launch(void* const* d_in, const int* in_sizes, int n_in,
                              void* d_out, int out_size) {
    const float* nrm   = (const float*)d_in[0];
    const float* light = (const float*)d_in[1];
    float* out = (float*)d_out;

    // 64 batches * 128 blocks = 8192 blocks, 256 threads, 2 groups/thread
    shading_kernel<<<8192, 256>>>(nrm, light, out);
}

// round 6
// speedup vs baseline: 1.1105x; 1.1105x over previous
#include <cuda_runtime.h>

// ShadingLayer: out[b,c,h,w] = sum_k L[b,c,k] * H_k(n[b,:,h,w])
// R5: persistent-segment pipelined streaming.
//   - 512 blocks: (batch, 1/8-batch segment); 16 loop iterations each.
//   - Two-phase A/B software pipeline: loads for the next phase are always
//     in flight while computing the current phase -> continuous DRAM demand.
//   - Coefficients folded once per block, held in registers.
//
// d_in[0]: recnormalch fp32 (64,3,512,512)
// d_in[1]: fc_light    fp32 (64,27)
// d_out  : fp32 (64,3,512,512)

#define C1f 0.8862269254527580f
#define C2f 1.0233267079464885f
#define C3f 0.2477079561003757f
#define C4f 0.8580855308097834f
#define C5f 0.4290427654048917f

static __device__ __forceinline__ float4 ldcs4(const float* p) {
    return __ldcs(reinterpret_cast<const float4*>(p));
}
static __device__ __forceinline__ void stcs4(float* p, float4 v) {
    __stcs(reinterpret_cast<float4*>(p), v);
}

#define HW (512 * 512)

// compute 4 pixels (one float4 triple) and store 3 channel float4s
static __device__ __forceinline__ void shade4(const float4 X, const float4 Y,
                                              const float4 Z,
                                              const float a[3][9], float* q) {
    const float xs[4] = {X.x, X.y, X.z, X.w};
    const float ys[4] = {Y.x, Y.y, Y.z, Y.w};
    const float zs[4] = {Z.x, Z.y, Z.z, Z.w};
    float o[3][4];
    #pragma unroll
    for (int j = 0; j < 4; j++) {
        const float x = xs[j], y = ys[j], z = zs[j];
        const float xx = x * x;
        const float yy = y * y;
        const float b5 = 2.0f * z * z - xx - yy;
        const float b6 = x * z;
        const float b7 = y * z;
        const float b8 = xx - yy;
        const float b9 = x * y;
        #pragma unroll
        for (int c = 0; c < 3; c++) {
            float r = a[c][0];
            r = fmaf(a[c][1], z,  r);
            r = fmaf(a[c][2], x,  r);
            r = fmaf(a[c][3], y,  r);
            r = fmaf(a[c][4], b5, r);
            r = fmaf(a[c][5], b6, r);
            r = fmaf(a[c][6], b7, r);
            r = fmaf(a[c][7], b8, r);
            r = fmaf(a[c][8], b9, r);
            o[c][j] = r;
        }
    }
    stcs4(q,          make_float4(o[0][0], o[0][1], o[0][2], o[0][3]));
    stcs4(q + HW,     make_float4(o[1][0], o[1][1], o[1][2], o[1][3]));
    stcs4(q + 2 * HW, make_float4(o[2][0], o[2][1], o[2][2], o[2][3]));
}

__global__ __launch_bounds__(256)
void shading_kernel(const float* __restrict__ nrm,
                    const float* __restrict__ light,
                    float* __restrict__ out) {
    // 65536 float4-groups per plane; 8 segments/batch -> 8192 groups/segment
    // per iteration a thread does groups (base+tid) [A] and (base+tid+256) [B];
    // 512 groups per iteration -> 16 iterations per segment.
    const unsigned bid = blockIdx.x;
    const int b   = bid >> 3;                 // batch
    const int seg = bid & 7;                  // segment within batch

    // ---- fold light coefficients once per block (registers) ----
    const float* Lb = light + b * 27;
    float a[3][9];
    #pragma unroll
    for (int c = 0; c < 3; c++) {
        a[c][0] = C1f * __ldg(Lb + 9 * c + 0);
        a[c][1] = C2f * __ldg(Lb + 9 * c + 1);
        a[c][2] = C2f * __ldg(Lb + 9 * c + 2);
        a[c][3] = C2f * __ldg(Lb + 9 * c + 3);
        a[c][4] = C3f * __ldg(Lb + 9 * c + 4);
        a[c][5] = C4f * __ldg(Lb + 9 * c + 5);
        a[c][6] = C4f * __ldg(Lb + 9 * c + 6);
        a[c][7] = C5f * __ldg(Lb + 9 * c + 7);
        a[c][8] = C4f * __ldg(Lb + 9 * c + 8);
    }

    const float* pA = nrm + (size_t)b * 3 * HW
                          + (size_t)(seg * 8192 + threadIdx.x) * 4;
    const float* pB = pA + 1024;              // +256 groups
    float* qA = out + (size_t)b * 3 * HW
                    + (size_t)(seg * 8192 + threadIdx.x) * 4;
    float* qB = qA + 1024;

    // ---- prologue: A(0) in flight ----
    float4 AX = ldcs4(pA);
    float4 AY = ldcs4(pA + HW);
    float4 AZ = ldcs4(pA + 2 * HW);

    #pragma unroll 1
    for (int i = 0; i < 16; i++) {
        // B(i) loads in flight while we compute A(i)
        float4 BX = ldcs4(pB);
        float4 BY = ldcs4(pB + HW);
        float4 BZ = ldcs4(pB + 2 * HW);

        shade4(AX, AY, AZ, a, qA);            // waits only on A scoreboard

        // A(i+1) loads in flight while we compute B(i)
        if (i < 15) {
            pA += 2048;                       // +512 groups
            AX = ldcs4(pA);
            AY = ldcs4(pA + HW);
            AZ = ldcs4(pA + 2 * HW);
        }

        shade4(BX, BY, BZ, a, qB);

        pB += 2048;
        qA += 2048;
        qB += 2048;
    }
}

extern "C" void kernel_launch(void* const* d_in, const int* in_sizes, int n_in,
                              void* d_out, int out_size) {
    const float* nrm   = (const float*)d_in[0];
    const float* light = (const float*)d_in[1];
    float* out = (float*)d_out;

    // 64 batches * 8 segments = 512 blocks, 256 threads, 16 iters each
    shading_kernel<<<512, 256>>>(nrm, light, out);
}

// round 7
// speedup vs baseline: 1.2913x; 1.1628x over previous
#include <cuda_runtime.h>

// ShadingLayer: out[b,c,h,w] = sum_k L[b,c,k] * H_k(n[b,:,h,w])
// R6 = R2 (2 float4-groups/thread, 6 front-batched LDG.128, streaming hints)
//      + block-shared coefficient fold (27 LDG per BLOCK, not per thread).
//      NO launch-bounds cap (R4's reg-cap spills were the regression cause).
//
// d_in[0]: recnormalch fp32 (64,3,512,512)
// d_in[1]: fc_light    fp32 (64,27)
// d_out  : fp32 (64,3,512,512)

#define C1f 0.8862269254527580f
#define C2f 1.0233267079464885f
#define C3f 0.2477079561003757f
#define C4f 0.8580855308097834f
#define C5f 0.4290427654048917f

static __device__ __forceinline__ float4 ldcs4(const float* p) {
    return __ldcs(reinterpret_cast<const float4*>(p));
}
static __device__ __forceinline__ void stcs4(float* p, float4 v) {
    __stcs(reinterpret_cast<float4*>(p), v);
}

__global__ __launch_bounds__(256)
void shading_kernel(const float* __restrict__ nrm,
                    const float* __restrict__ light,
                    float* __restrict__ out) {
    constexpr int HW = 512 * 512;          // pixels per plane
    // 65536 float4-groups/plane; 512 groups per block -> 128 blocks/batch
    const unsigned bid = blockIdx.x;
    const int b   = bid >> 7;              // batch
    const int blk = bid & 127;             // block within batch
    const int v0  = blk * 512 + threadIdx.x;

    // ---- issue all 6 data loads FIRST (independent of smem fold) ----
    const float* p0 = nrm + (size_t)b * 3 * HW + (size_t)v0 * 4;
    const float* p1 = p0 + 1024;           // +256 groups
    float4 X0 = ldcs4(p0);
    float4 Y0 = ldcs4(p0 + HW);
    float4 Z0 = ldcs4(p0 + 2 * HW);
    float4 X1 = ldcs4(p1);
    float4 Y1 = ldcs4(p1 + HW);
    float4 Z1 = ldcs4(p1 + 2 * HW);

    // ---- block-cooperative coefficient load + fold (27 LDG / block) ----
    __shared__ float sa[27];
    if (threadIdx.x < 27) {
        const int k = threadIdx.x % 9;
        const float ck = (k == 0) ? C1f
                       : (k <= 3) ? C2f
                       : (k == 4) ? C3f
                       : (k == 7) ? C5f
                       : C4f;              // k = 5,6,8
        sa[threadIdx.x] = ck * __ldg(light + b * 27 + threadIdx.x);
    }
    __syncthreads();                       // hides under in-flight DRAM loads

    float a[3][9];
    #pragma unroll
    for (int i = 0; i < 27; i++) a[i / 9][i % 9] = sa[i];

    // store base derived from load base (single offset chain)
    float* q0 = out + (p0 - nrm);

    #pragma unroll
    for (int g = 0; g < 2; g++) {
        const float4 X = g ? X1 : X0;
        const float4 Y = g ? Y1 : Y0;
        const float4 Z = g ? Z1 : Z0;
        const float xs[4] = {X.x, X.y, X.z, X.w};
        const float ys[4] = {Y.x, Y.y, Y.z, Y.w};
        const float zs[4] = {Z.x, Z.y, Z.z, Z.w};
        float o[3][4];

        #pragma unroll
        for (int j = 0; j < 4; j++) {
            const float x = xs[j], y = ys[j], z = zs[j];
            const float xx = x * x;
            const float yy = y * y;
            const float b5 = 2.0f * z * z - xx - yy;
            const float b6 = x * z;
            const float b7 = y * z;
            const float b8 = xx - yy;
            const float b9 = x * y;
            #pragma unroll
            for (int c = 0; c < 3; c++) {
                float r = a[c][0];
                r = fmaf(a[c][1], z,  r);
                r = fmaf(a[c][2], x,  r);
                r = fmaf(a[c][3], y,  r);
                r = fmaf(a[c][4], b5, r);
                r = fmaf(a[c][5], b6, r);
                r = fmaf(a[c][6], b7, r);
                r = fmaf(a[c][7], b8, r);
                r = fmaf(a[c][8], b9, r);
                o[c][j] = r;
            }
        }

        float* q = g ? (q0 + 1024) : q0;
        stcs4(q,          make_float4(o[0][0], o[0][1], o[0][2], o[0][3]));
        stcs4(q + HW,     make_float4(o[1][0], o[1][1], o[1][2], o[1][3]));
        stcs4(q + 2 * HW, make_float4(o[2][0], o[2][1], o[2][2], o[2][3]));
    }
}

extern "C" void kernel_launch(void* const* d_in, const int* in_sizes, int n_in,
                              void* d_out, int out_size) {
    const float* nrm   = (const float*)d_in[0];
    const float* light = (const float*)d_in[1];
    float* out = (float*)d_out;

    // 64 batches * 128 blocks = 8192 blocks, 256 threads, 2 groups/thread
    shading_kernel<<<8192, 256>>>(nrm, light, out);
}